// round 3
// baseline (speedup 1.0000x reference)
#include <cuda_runtime.h>
#include <cuda_bf16.h>

#define NUM_GRAPHS 2048
#define MAX_ATOMS  200000

// Packed per-atom tag: (batch << 4) | z.  batch < 2048 (11 bits), z in 1..10 (4 bits).
__device__ unsigned short g_bz[MAX_ATOMS];

__global__ void pack_tags_kernel(const int* __restrict__ z,
                                 const int* __restrict__ batch,
                                 int n_atoms) {
    int i = blockIdx.x * blockDim.x + threadIdx.x;
    if (i < n_atoms) {
        g_bz[i] = (unsigned short)((batch[i] << 4) | z[i]);
    }
}

__global__ void zero_out_kernel(float* __restrict__ out, int n) {
    int i = blockIdx.x * blockDim.x + threadIdx.x;
    if (i < n) out[i] = 0.0f;
}

__global__ void repulsion_kernel(const float* __restrict__ pos,
                                 const float* __restrict__ arep,
                                 const float* __restrict__ zeff,
                                 const int*   __restrict__ src_idx,
                                 const int*   __restrict__ dst_idx,
                                 float*       __restrict__ out,
                                 int n_edges4,   // number of int4 packs
                                 int n_rem,      // leftover edges (< 4)
                                 int n_edges)    // total edges
{
    const float AA2AU   = 1.8897261258369282f;
    const float AU2KCAL = 627.5094740630558f;

    int t = blockIdx.x * blockDim.x + threadIdx.x;
    if (t < n_edges4) {
        int4 s4 = ((const int4*)src_idx)[t];
        int4 d4 = ((const int4*)dst_idx)[t];
        const int ss[4] = {s4.x, s4.y, s4.z, s4.w};
        const int dd[4] = {d4.x, d4.y, d4.z, d4.w};
        #pragma unroll
        for (int k = 0; k < 4; k++) {
            int s = ss[k];
            int d = dd[k];
            unsigned short bs = __ldg(&g_bz[s]);
            unsigned short bd = __ldg(&g_bz[d]);
            if ((bs >> 4) == (bd >> 4)) {
                // Rare path (~1/2048 of edges)
                float psx = __ldg(&pos[3 * s + 0]);
                float psy = __ldg(&pos[3 * s + 1]);
                float psz = __ldg(&pos[3 * s + 2]);
                float pdx = __ldg(&pos[3 * d + 0]);
                float pdy = __ldg(&pos[3 * d + 1]);
                float pdz = __ldg(&pos[3 * d + 2]);
                float dx = psx - pdx, dy = psy - pdy, dz = psz - pdz;
                float d2 = dx * dx + dy * dy + dz * dz;
                if (d2 <= 9.0f) {
                    float dist = fmaxf(sqrtf(d2), 1e-9f);
                    float dau  = dist * AA2AU;
                    int zs = bs & 15, zd = bd & 15;
                    float at  = sqrtf(__ldg(&arep[zs]) * __ldg(&arep[zd]));
                    float rep = __ldg(&zeff[zs]) * __ldg(&zeff[zd]) *
                                expf(-at * dau * sqrtf(dau)) / dau;
                    atomicAdd(&out[bs >> 4], rep * AU2KCAL);
                }
            }
        }
    }

    // Scalar tail (edges not covered by int4 packs)
    if (blockIdx.x == 0 && (int)threadIdx.x < n_rem) {
        int e = n_edges4 * 4 + threadIdx.x;
        int s = src_idx[e];
        int d = dst_idx[e];
        unsigned short bs = g_bz[s];
        unsigned short bd = g_bz[d];
        if ((bs >> 4) == (bd >> 4)) {
            float dx = pos[3 * s + 0] - pos[3 * d + 0];
            float dy = pos[3 * s + 1] - pos[3 * d + 1];
            float dz = pos[3 * s + 2] - pos[3 * d + 2];
            float d2 = dx * dx + dy * dy + dz * dz;
            if (d2 <= 9.0f) {
                float dist = fmaxf(sqrtf(d2), 1e-9f);
                float dau  = dist * AA2AU;
                int zs = bs & 15, zd = bd & 15;
                float at  = sqrtf(arep[zs] * arep[zd]);
                float rep = zeff[zs] * zeff[zd] *
                            expf(-at * dau * sqrtf(dau)) / dau;
                atomicAdd(&out[bs >> 4], rep * AU2KCAL);
            }
        }
    }
}

extern "C" void kernel_launch(void* const* d_in, const int* in_sizes, int n_in,
                              void* d_out, int out_size) {
    const float* pos        = (const float*)d_in[0];
    const float* arep       = (const float*)d_in[1];
    const float* zeff       = (const float*)d_in[2];
    const int*   z          = (const int*)d_in[3];
    const int*   edge_index = (const int*)d_in[4];
    const int*   batch      = (const int*)d_in[5];
    float*       out        = (float*)d_out;

    int n_atoms = in_sizes[3];
    int n_edges = in_sizes[4] / 2;
    const int* src_idx = edge_index;
    const int* dst_idx = edge_index + n_edges;

    // 1) zero the output (poisoned by harness)
    zero_out_kernel<<<(out_size + 255) / 256, 256>>>(out, out_size);

    // 2) pack (batch, z) into uint16 side table
    pack_tags_kernel<<<(n_atoms + 255) / 256, 256>>>(z, batch, n_atoms);

    // 3) main edge filter + rare-path physics
    int n_edges4 = n_edges >> 2;
    int n_rem    = n_edges & 3;
    int threads  = 256;
    int blocks   = (n_edges4 + threads - 1) / threads;
    if (blocks < 1) blocks = 1;
    repulsion_kernel<<<blocks, threads>>>(pos, arep, zeff, src_idx, dst_idx,
                                          out, n_edges4, n_rem, n_edges);
}

// round 4
// speedup vs baseline: 2.2593x; 2.2593x over previous
#include <cuda_runtime.h>
#include <cuda_bf16.h>

#define NUM_GRAPHS 2048
#define MAX_ATOMS  200000

// Packed per-atom tag: (batch << 4) | z.  batch < 2048 (11 bits), z in 1..10 (4 bits).
__device__ unsigned short g_bz[MAX_ATOMS];
__device__ int g_cnt[NUM_GRAPHS];   // atoms per graph
__device__ int g_maxd;              // max graph size (prefilter radius)

// Kernel 1: zero output + counters + maxd
__global__ void init_kernel(float* __restrict__ out, int out_n) {
    int i = blockIdx.x * blockDim.x + threadIdx.x;
    if (i < out_n)      out[i]  = 0.0f;
    if (i < NUM_GRAPHS) g_cnt[i] = 0;
    if (i == 0)         g_maxd  = 1;
}

// Kernel 2: pack (batch, z) tags + count atoms per graph
__global__ void pack_tags_kernel(const int* __restrict__ z,
                                 const int* __restrict__ batch,
                                 int n_atoms) {
    int i = blockIdx.x * blockDim.x + threadIdx.x;
    if (i < n_atoms) {
        int b = batch[i];
        g_bz[i] = (unsigned short)((b << 4) | z[i]);
        atomicAdd(&g_cnt[b], 1);
    }
}

// Kernel 3: max-reduce graph sizes -> g_maxd  (single block, 1024 threads)
__global__ void max_kernel() {
    __shared__ int sm[1024];
    int t = threadIdx.x;
    int v = g_cnt[t];
    int v2 = g_cnt[t + 1024];
    sm[t] = v > v2 ? v : v2;
    __syncthreads();
    for (int s = 512; s > 0; s >>= 1) {
        if (t < s) { int o = sm[t + s]; if (o > sm[t]) sm[t] = o; }
        __syncthreads();
    }
    if (t == 0) g_maxd = sm[0] > 1 ? sm[0] : 1;
}

// Kernel 4: main edge stream. Gather-free distance prefilter, rare-path physics.
__global__ void repulsion_kernel(const float* __restrict__ pos,
                                 const float* __restrict__ arep,
                                 const float* __restrict__ zeff,
                                 const int*   __restrict__ src_idx,
                                 const int*   __restrict__ dst_idx,
                                 float*       __restrict__ out,
                                 int n_edges4,   // number of int4 packs
                                 int n_rem)      // leftover edges (< 4)
{
    const float AA2AU   = 1.8897261258369282f;
    const float AU2KCAL = 627.5094740630558f;

    const int D = g_maxd;   // same-graph => |src-dst| < D (batch is sorted)

    int t = blockIdx.x * blockDim.x + threadIdx.x;
    if (t < n_edges4) {
        int4 s4 = ((const int4*)src_idx)[t];
        int4 d4 = ((const int4*)dst_idx)[t];
        const int ss[4] = {s4.x, s4.y, s4.z, s4.w};
        const int dd[4] = {d4.x, d4.y, d4.z, d4.w};
        #pragma unroll
        for (int k = 0; k < 4; k++) {
            int s = ss[k];
            int d = dd[k];
            if (abs(s - d) < D) {                       // cheap prefilter, no memory
                unsigned short bs = __ldg(&g_bz[s]);
                unsigned short bd = __ldg(&g_bz[d]);
                if ((bs >> 4) == (bd >> 4)) {           // exact same-graph check
                    float psx = __ldg(&pos[3 * s + 0]);
                    float psy = __ldg(&pos[3 * s + 1]);
                    float psz = __ldg(&pos[3 * s + 2]);
                    float pdx = __ldg(&pos[3 * d + 0]);
                    float pdy = __ldg(&pos[3 * d + 1]);
                    float pdz = __ldg(&pos[3 * d + 2]);
                    float dx = psx - pdx, dy = psy - pdy, dz = psz - pdz;
                    float d2 = dx * dx + dy * dy + dz * dz;
                    if (d2 <= 9.0f) {
                        float dist = fmaxf(sqrtf(d2), 1e-9f);
                        float dau  = dist * AA2AU;
                        int zs = bs & 15, zd = bd & 15;
                        float at  = sqrtf(__ldg(&arep[zs]) * __ldg(&arep[zd]));
                        float rep = __ldg(&zeff[zs]) * __ldg(&zeff[zd]) *
                                    expf(-at * dau * sqrtf(dau)) / dau;
                        atomicAdd(&out[bs >> 4], rep * AU2KCAL);
                    }
                }
            }
        }
    }

    // Scalar tail (edges not covered by int4 packs)
    if (blockIdx.x == 0 && (int)threadIdx.x < n_rem) {
        int e = n_edges4 * 4 + threadIdx.x;
        int s = src_idx[e];
        int d = dst_idx[e];
        unsigned short bs = g_bz[s];
        unsigned short bd = g_bz[d];
        if ((bs >> 4) == (bd >> 4)) {
            float dx = pos[3 * s + 0] - pos[3 * d + 0];
            float dy = pos[3 * s + 1] - pos[3 * d + 1];
            float dz = pos[3 * s + 2] - pos[3 * d + 2];
            float d2 = dx * dx + dy * dy + dz * dz;
            if (d2 <= 9.0f) {
                float dist = fmaxf(sqrtf(d2), 1e-9f);
                float dau  = dist * AA2AU;
                int zs = bs & 15, zd = bd & 15;
                float at  = sqrtf(arep[zs] * arep[zd]);
                float rep = zeff[zs] * zeff[zd] *
                            expf(-at * dau * sqrtf(dau)) / dau;
                atomicAdd(&out[bs >> 4], rep * AU2KCAL);
            }
        }
    }
}

extern "C" void kernel_launch(void* const* d_in, const int* in_sizes, int n_in,
                              void* d_out, int out_size) {
    const float* pos        = (const float*)d_in[0];
    const float* arep       = (const float*)d_in[1];
    const float* zeff       = (const float*)d_in[2];
    const int*   z          = (const int*)d_in[3];
    const int*   edge_index = (const int*)d_in[4];
    const int*   batch      = (const int*)d_in[5];
    float*       out        = (float*)d_out;

    int n_atoms = in_sizes[3];
    int n_edges = in_sizes[4] / 2;
    const int* src_idx = edge_index;
    const int* dst_idx = edge_index + n_edges;

    // 1) zero output + per-graph counters
    int init_n = out_size > NUM_GRAPHS ? out_size : NUM_GRAPHS;
    init_kernel<<<(init_n + 255) / 256, 256>>>(out, out_size);

    // 2) pack (batch, z) tags + count atoms per graph
    pack_tags_kernel<<<(n_atoms + 255) / 256, 256>>>(z, batch, n_atoms);

    // 3) max graph size -> prefilter radius
    max_kernel<<<1, 1024>>>();

    // 4) main edge stream
    int n_edges4 = n_edges >> 2;
    int n_rem    = n_edges & 3;
    int threads  = 256;
    int blocks   = (n_edges4 + threads - 1) / threads;
    if (blocks < 1) blocks = 1;
    repulsion_kernel<<<blocks, threads>>>(pos, arep, zeff, src_idx, dst_idx,
                                          out, n_edges4, n_rem);
}